// round 1
// baseline (speedup 1.0000x reference)
#include <cuda_runtime.h>
#include <math.h>

// Problem constants
#define SPOS 8192      // T*H*W = 8*32*32
#define CCH  512
#define TT   8
#define HH   32
#define WW   32

// ---------------- scratch (static device memory; no allocations) ----------------
__device__ float g_n[SPOS * CCH];   // normalized / silu'ed activations
__device__ float g_h[SPOS * CCH];   // conv intermediate / y2
__device__ float g_y[SPOS * CCH];   // resnet1 output (attn residual)
__device__ float g_q[SPOS * CCH];
__device__ float g_k[SPOS * CCH];
__device__ float g_v[SPOS * CCH];
__device__ float g_o[SPOS * CCH];
__device__ float g_s[67108864];     // 8192x8192 attention scores (256 MB)

// ---------------- reductions ----------------
__device__ __forceinline__ float warpReduceSum(float v) {
#pragma unroll
    for (int o = 16; o; o >>= 1) v += __shfl_xor_sync(0xffffffffu, v, o);
    return v;
}
__device__ __forceinline__ float warpReduceMax(float v) {
#pragma unroll
    for (int o = 16; o; o >>= 1) v = fmaxf(v, __shfl_xor_sync(0xffffffffu, v, o));
    return v;
}

// ---------------- rmsnorm (+optional silu) ----------------
// out = x / (||x||_2 + 1e-8) * sqrt(C) * gamma ; optionally silu()
__global__ __launch_bounds__(128) void rmsnorm_kernel(
    const float* __restrict__ x, const float* __restrict__ g,
    float* __restrict__ out, int do_silu)
{
    __shared__ float red[4];
    const int r = blockIdx.x;
    const int tid = threadIdx.x;
    const float4 v = *(const float4*)(x + (size_t)r * CCH + tid * 4);
    float ss = v.x * v.x + v.y * v.y + v.z * v.z + v.w * v.w;
    ss = warpReduceSum(ss);
    if ((tid & 31) == 0) red[tid >> 5] = ss;
    __syncthreads();
    const float tot = red[0] + red[1] + red[2] + red[3];
    const float scale = 22.62741699796952f / (sqrtf(tot) + 1e-8f); // sqrt(512)
    const float4 gg = *(const float4*)(g + tid * 4);
    float4 o;
    o.x = v.x * scale * gg.x;
    o.y = v.y * scale * gg.y;
    o.z = v.z * scale * gg.z;
    o.w = v.w * scale * gg.w;
    if (do_silu) {
        o.x = o.x / (1.0f + __expf(-o.x));
        o.y = o.y / (1.0f + __expf(-o.y));
        o.z = o.z / (1.0f + __expf(-o.z));
        o.w = o.w / (1.0f + __expf(-o.w));
    }
    *(float4*)(out + (size_t)r * CCH + tid * 4) = o;
}

// ---------------- GEMM tile config ----------------
#define BM 128
#define BN 128
#define BK 8

// C[M,N] = A[M,K] (row-major, stride lda) * B[K,N] (row-major, stride ldb) (+bias)(+resid)
// varK: per-M-tile effective K = (frame(m0)+1)*1024 (for attention A*V)
__global__ __launch_bounds__(256, 2) void gemm_nn_kernel(
    const float* __restrict__ A, int lda,
    const float* __restrict__ B, int ldb,
    const float* __restrict__ bias,
    const float* __restrict__ resid,
    float* __restrict__ C, int ldc,
    int K, int varK)
{
    __shared__ float As[BK][BM];
    __shared__ float Bs[BK][BN];
    const int tid = threadIdx.x;
    const int m0 = blockIdx.y * BM, n0 = blockIdx.x * BN;
    if (varK) K = ((m0 >> 10) + 1) << 10;
    const int tx = tid & 15, ty = tid >> 4;
    const int am = tid >> 1, aj = (tid & 1) << 2;
    const int bj = tid >> 5, bn = (tid & 31) << 2;

    float acc[2][2][4][4];
#pragma unroll
    for (int a = 0; a < 2; a++)
#pragma unroll
        for (int b = 0; b < 2; b++)
#pragma unroll
            for (int i = 0; i < 4; i++)
#pragma unroll
                for (int j = 0; j < 4; j++) acc[a][b][i][j] = 0.0f;

    const float* Aptr = A + (size_t)(m0 + am) * lda + aj;
    const float* Bptr = B + (size_t)bj * ldb + n0 + bn;

    for (int kk = 0; kk < K; kk += BK) {
        const float4 av = *(const float4*)(Aptr + kk);
        const float4 bv = *(const float4*)(Bptr + (size_t)kk * ldb);
        __syncthreads();
        As[aj + 0][am] = av.x; As[aj + 1][am] = av.y;
        As[aj + 2][am] = av.z; As[aj + 3][am] = av.w;
        *(float4*)&Bs[bj][bn] = bv;
        __syncthreads();
#pragma unroll
        for (int p = 0; p < BK; ++p) {
            float a[2][4], b[2][4];
            *(float4*)a[0] = *(const float4*)&As[p][ty * 4];
            *(float4*)a[1] = *(const float4*)&As[p][64 + ty * 4];
            *(float4*)b[0] = *(const float4*)&Bs[p][tx * 4];
            *(float4*)b[1] = *(const float4*)&Bs[p][64 + tx * 4];
#pragma unroll
            for (int rr = 0; rr < 2; rr++)
#pragma unroll
                for (int i = 0; i < 4; i++)
#pragma unroll
                    for (int cc = 0; cc < 2; cc++)
#pragma unroll
                        for (int j = 0; j < 4; j++)
                            acc[rr][cc][i][j] += a[rr][i] * b[cc][j];
        }
    }

#pragma unroll
    for (int rr = 0; rr < 2; rr++)
#pragma unroll
        for (int i = 0; i < 4; i++) {
            const int m = m0 + rr * 64 + ty * 4 + i;
#pragma unroll
            for (int cc = 0; cc < 2; cc++) {
                const int n = n0 + cc * 64 + tx * 4;
                float4 o;
                o.x = acc[rr][cc][i][0]; o.y = acc[rr][cc][i][1];
                o.z = acc[rr][cc][i][2]; o.w = acc[rr][cc][i][3];
                if (bias) {
                    const float4 bb = *(const float4*)(bias + n);
                    o.x += bb.x; o.y += bb.y; o.z += bb.z; o.w += bb.w;
                }
                if (resid) {
                    const float4 rv = *(const float4*)(resid + (size_t)m * ldc + n);
                    o.x += rv.x; o.y += rv.y; o.z += rv.z; o.w += rv.w;
                }
                *(float4*)(C + (size_t)m * ldc + n) = o;
            }
        }
}

// S[M,N] = Q[M,512] * K[N,512]^T * scale, block-causal skip (frame = idx/1024)
__global__ __launch_bounds__(256, 2) void gemm_nt_kernel(
    const float* __restrict__ Q, const float* __restrict__ Kmat,
    float* __restrict__ S)
{
    const int m0 = blockIdx.y * BM, n0 = blockIdx.x * BN;
    const int qf = m0 >> 10;
    if (n0 >= ((qf + 1) << 10)) return;   // keys beyond causal frame horizon

    __shared__ float As[BK][BM];
    __shared__ float Bs[BK][BN];
    const int tid = threadIdx.x;
    const int tx = tid & 15, ty = tid >> 4;
    const int am = tid >> 1, aj = (tid & 1) << 2;

    float acc[2][2][4][4];
#pragma unroll
    for (int a = 0; a < 2; a++)
#pragma unroll
        for (int b = 0; b < 2; b++)
#pragma unroll
            for (int i = 0; i < 4; i++)
#pragma unroll
                for (int j = 0; j < 4; j++) acc[a][b][i][j] = 0.0f;

    const float* Aptr = Q + (size_t)(m0 + am) * CCH + aj;
    const float* Bptr = Kmat + (size_t)(n0 + am) * CCH + aj;

    for (int kk = 0; kk < CCH; kk += BK) {
        const float4 av = *(const float4*)(Aptr + kk);
        const float4 bv = *(const float4*)(Bptr + kk);
        __syncthreads();
        As[aj + 0][am] = av.x; As[aj + 1][am] = av.y;
        As[aj + 2][am] = av.z; As[aj + 3][am] = av.w;
        Bs[aj + 0][am] = bv.x; Bs[aj + 1][am] = bv.y;
        Bs[aj + 2][am] = bv.z; Bs[aj + 3][am] = bv.w;
        __syncthreads();
#pragma unroll
        for (int p = 0; p < BK; ++p) {
            float a[2][4], b[2][4];
            *(float4*)a[0] = *(const float4*)&As[p][ty * 4];
            *(float4*)a[1] = *(const float4*)&As[p][64 + ty * 4];
            *(float4*)b[0] = *(const float4*)&Bs[p][tx * 4];
            *(float4*)b[1] = *(const float4*)&Bs[p][64 + tx * 4];
#pragma unroll
            for (int rr = 0; rr < 2; rr++)
#pragma unroll
                for (int i = 0; i < 4; i++)
#pragma unroll
                    for (int cc = 0; cc < 2; cc++)
#pragma unroll
                        for (int j = 0; j < 4; j++)
                            acc[rr][cc][i][j] += a[rr][i] * b[cc][j];
        }
    }

    const float SCALE = 0.04419417382415922f; // 1/sqrt(512)
#pragma unroll
    for (int rr = 0; rr < 2; rr++)
#pragma unroll
        for (int i = 0; i < 4; i++) {
            const int m = m0 + rr * 64 + ty * 4 + i;
#pragma unroll
            for (int cc = 0; cc < 2; cc++) {
                const int n = n0 + cc * 64 + tx * 4;
                float4 o;
                o.x = acc[rr][cc][i][0] * SCALE; o.y = acc[rr][cc][i][1] * SCALE;
                o.z = acc[rr][cc][i][2] * SCALE; o.w = acc[rr][cc][i][3] * SCALE;
                *(float4*)(S + (size_t)m * SPOS + n) = o;
            }
        }
}

// ---------------- implicit-GEMM causal conv3d (3x3x3, edge pad t(2,0) hw(1,1)) ----------------
__global__ __launch_bounds__(256, 2) void conv_gemm_kernel(
    const float* __restrict__ in, const float* __restrict__ wgt,
    const float* __restrict__ bias, const float* __restrict__ resid,
    float* __restrict__ out)
{
    __shared__ float As[BK][BM];
    __shared__ float Bs[BK][BN];
    __shared__ int sBase[BM * 27];
    const int tid = threadIdx.x;
    const int m0 = blockIdx.y * BM, n0 = blockIdx.x * BN;

    for (int i = tid; i < BM * 27; i += 256) {
        const int mloc = i / 27;
        const int tap = i - mloc * 27;
        const int m = m0 + mloc;
        const int kt = tap / 9, r9 = tap - kt * 9;
        const int kh = r9 / 3, kw = r9 - kh * 3;
        const int t = m >> 10, hw = m & 1023, h = hw >> 5, w = hw & 31;
        int tin = t + kt - 2; tin = tin < 0 ? 0 : tin;
        int hin = h + kh - 1; hin = hin < 0 ? 0 : (hin > 31 ? 31 : hin);
        int win = w + kw - 1; win = win < 0 ? 0 : (win > 31 ? 31 : win);
        sBase[i] = ((tin << 10) + (hin << 5) + win) << 9; // *512 channels
    }
    __syncthreads();

    const int tx = tid & 15, ty = tid >> 4;
    const int am = tid >> 1, aj = (tid & 1) << 2;
    const int bj = tid >> 5, bn = (tid & 31) << 2;

    float acc[2][2][4][4];
#pragma unroll
    for (int a = 0; a < 2; a++)
#pragma unroll
        for (int b = 0; b < 2; b++)
#pragma unroll
            for (int i = 0; i < 4; i++)
#pragma unroll
                for (int j = 0; j < 4; j++) acc[a][b][i][j] = 0.0f;

    for (int kk = 0; kk < 27 * CCH; kk += BK) {
        const int tap = kk >> 9;
        const int cin = (kk & 511) + aj;
        const float4 av = *(const float4*)(in + sBase[am * 27 + tap] + cin);
        const float4 bv = *(const float4*)(wgt + (size_t)(kk + bj) * CCH + n0 + bn);
        __syncthreads();
        As[aj + 0][am] = av.x; As[aj + 1][am] = av.y;
        As[aj + 2][am] = av.z; As[aj + 3][am] = av.w;
        *(float4*)&Bs[bj][bn] = bv;
        __syncthreads();
#pragma unroll
        for (int p = 0; p < BK; ++p) {
            float a[2][4], b[2][4];
            *(float4*)a[0] = *(const float4*)&As[p][ty * 4];
            *(float4*)a[1] = *(const float4*)&As[p][64 + ty * 4];
            *(float4*)b[0] = *(const float4*)&Bs[p][tx * 4];
            *(float4*)b[1] = *(const float4*)&Bs[p][64 + tx * 4];
#pragma unroll
            for (int rr = 0; rr < 2; rr++)
#pragma unroll
                for (int i = 0; i < 4; i++)
#pragma unroll
                    for (int cc = 0; cc < 2; cc++)
#pragma unroll
                        for (int j = 0; j < 4; j++)
                            acc[rr][cc][i][j] += a[rr][i] * b[cc][j];
        }
    }

#pragma unroll
    for (int rr = 0; rr < 2; rr++)
#pragma unroll
        for (int i = 0; i < 4; i++) {
            const int m = m0 + rr * 64 + ty * 4 + i;
#pragma unroll
            for (int cc = 0; cc < 2; cc++) {
                const int n = n0 + cc * 64 + tx * 4;
                float4 o;
                o.x = acc[rr][cc][i][0]; o.y = acc[rr][cc][i][1];
                o.z = acc[rr][cc][i][2]; o.w = acc[rr][cc][i][3];
                const float4 bb = *(const float4*)(bias + n);
                o.x += bb.x; o.y += bb.y; o.z += bb.z; o.w += bb.w;
                if (resid) {
                    const float4 rv = *(const float4*)(resid + (size_t)m * CCH + n);
                    o.x += rv.x; o.y += rv.y; o.z += rv.z; o.w += rv.w;
                }
                *(float4*)(out + (size_t)m * CCH + n) = o;
            }
        }
}

// ---------------- row softmax over block-causal scores ----------------
__global__ __launch_bounds__(256) void softmax_kernel(float* __restrict__ S)
{
    __shared__ float red[8];
    const int r = blockIdx.x, tid = threadIdx.x;
    const int cnt = (((r >> 10) + 1) << 10) >> 8;  // L/256, L=(frame+1)*1024
    float* row = S + (size_t)r * SPOS;

    float vals[32];
    float mx = -3.4e38f;
#pragma unroll
    for (int i = 0; i < 32; i++)
        if (i < cnt) { vals[i] = row[i * 256 + tid]; mx = fmaxf(mx, vals[i]); }
    mx = warpReduceMax(mx);
    if ((tid & 31) == 0) red[tid >> 5] = mx;
    __syncthreads();
    float m2 = red[0];
#pragma unroll
    for (int i = 1; i < 8; i++) m2 = fmaxf(m2, red[i]);
    __syncthreads();

    float sum = 0.0f;
#pragma unroll
    for (int i = 0; i < 32; i++)
        if (i < cnt) { vals[i] = __expf(vals[i] - m2); sum += vals[i]; }
    sum = warpReduceSum(sum);
    if ((tid & 31) == 0) red[tid >> 5] = sum;
    __syncthreads();
    float tot = 0.0f;
#pragma unroll
    for (int i = 0; i < 8; i++) tot += red[i];
    const float inv = 1.0f / tot;
#pragma unroll
    for (int i = 0; i < 32; i++)
        if (i < cnt) row[i * 256 + tid] = vals[i] * inv;
}

// ---------------- host orchestration ----------------
extern "C" void kernel_launch(void* const* d_in, const int* in_sizes, int n_in,
                              void* d_out, int out_size)
{
    const float* x    = (const float*)d_in[0];
    const float* r1g1 = (const float*)d_in[1];
    const float* r1w1 = (const float*)d_in[2];
    const float* r1b1 = (const float*)d_in[3];
    const float* r1g2 = (const float*)d_in[4];
    const float* r1w2 = (const float*)d_in[5];
    const float* r1b2 = (const float*)d_in[6];
    const float* atg  = (const float*)d_in[7];
    const float* qw   = (const float*)d_in[8];
    const float* qb   = (const float*)d_in[9];
    const float* kw   = (const float*)d_in[10];
    const float* kb   = (const float*)d_in[11];
    const float* vw   = (const float*)d_in[12];
    const float* vb   = (const float*)d_in[13];
    const float* pw   = (const float*)d_in[14];
    const float* pb   = (const float*)d_in[15];
    const float* r2g1 = (const float*)d_in[16];
    const float* r2w1 = (const float*)d_in[17];
    const float* r2b1 = (const float*)d_in[18];
    const float* r2g2 = (const float*)d_in[19];
    const float* r2w2 = (const float*)d_in[20];
    const float* r2b2 = (const float*)d_in[21];
    float* out = (float*)d_out;

    float *n, *h, *y, *q, *k, *v, *o, *s;
    cudaGetSymbolAddress((void**)&n, g_n);
    cudaGetSymbolAddress((void**)&h, g_h);
    cudaGetSymbolAddress((void**)&y, g_y);
    cudaGetSymbolAddress((void**)&q, g_q);
    cudaGetSymbolAddress((void**)&k, g_k);
    cudaGetSymbolAddress((void**)&v, g_v);
    cudaGetSymbolAddress((void**)&o, g_o);
    cudaGetSymbolAddress((void**)&s, g_s);

    const dim3 gemmGrid(CCH / BN, SPOS / BM);   // (4, 64)
    const dim3 ntGrid(SPOS / BN, SPOS / BM);    // (64, 64)

    // ---- resnet 1 ----
    rmsnorm_kernel<<<SPOS, 128>>>(x, r1g1, n, 1);
    conv_gemm_kernel<<<gemmGrid, 256>>>(n, r1w1, r1b1, nullptr, h);
    rmsnorm_kernel<<<SPOS, 128>>>(h, r1g2, n, 1);
    conv_gemm_kernel<<<gemmGrid, 256>>>(n, r1w2, r1b2, x, y);   // y1 = conv + x

    // ---- attention ----
    rmsnorm_kernel<<<SPOS, 128>>>(y, atg, n, 0);
    gemm_nn_kernel<<<gemmGrid, 256>>>(n, CCH, qw, CCH, qb, nullptr, q, CCH, CCH, 0);
    gemm_nn_kernel<<<gemmGrid, 256>>>(n, CCH, kw, CCH, kb, nullptr, k, CCH, CCH, 0);
    gemm_nn_kernel<<<gemmGrid, 256>>>(n, CCH, vw, CCH, vb, nullptr, v, CCH, CCH, 0);
    gemm_nt_kernel<<<ntGrid, 256>>>(q, k, s);
    softmax_kernel<<<SPOS, 256>>>(s);
    gemm_nn_kernel<<<gemmGrid, 256>>>(s, SPOS, v, CCH, nullptr, nullptr, o, CCH, SPOS, 1);
    gemm_nn_kernel<<<gemmGrid, 256>>>(o, CCH, pw, CCH, pb, y, h, CCH, CCH, 0);  // y2 = proj + y1 -> h

    // ---- resnet 2 ----
    rmsnorm_kernel<<<SPOS, 128>>>(h, r2g1, n, 1);
    conv_gemm_kernel<<<gemmGrid, 256>>>(n, r2w1, r2b1, nullptr, o);
    rmsnorm_kernel<<<SPOS, 128>>>(o, r2g2, n, 1);
    conv_gemm_kernel<<<gemmGrid, 256>>>(n, r2w2, r2b2, h, out);  // final = conv + y2
}

// round 3
// speedup vs baseline: 2.9899x; 2.9899x over previous
#include <cuda_runtime.h>
#include <cuda_bf16.h>
#include <cstdint>
#include <math.h>

#define SPOS 8192
#define CCH  512
#define CONVK 13824   // 27*512

typedef __nv_bfloat16 bf16;

// ---------------- scratch (static device memory) ----------------
__device__ __align__(256) bf16 g_nHi[SPOS*CCH], g_nLo[SPOS*CCH];
__device__ __align__(256) bf16 g_wHi[CONVK*CCH], g_wLo[CONVK*CCH];
__device__ __align__(256) bf16 g_qHi[SPOS*CCH], g_qLo[SPOS*CCH];
__device__ __align__(256) bf16 g_kHi[SPOS*CCH], g_kLo[SPOS*CCH];
__device__ __align__(256) bf16 g_vtHi[SPOS*CCH], g_vtLo[SPOS*CCH];
__device__ __align__(256) bf16 g_pHi[(size_t)SPOS*SPOS], g_pLo[(size_t)SPOS*SPOS];
__device__ __align__(256) float g_s[(size_t)SPOS*SPOS];
__device__ __align__(256) float g_t[SPOS*CCH], g_h[SPOS*CCH], g_y[SPOS*CCH];

// ---------------- helpers ----------------
__device__ __forceinline__ uint32_t smem_u32(const void* p) {
    uint32_t a;
    asm("{ .reg .u64 t; cvta.to.shared.u64 t, %1; cvt.u32.u64 %0, t; }" : "=r"(a) : "l"(p));
    return a;
}
__device__ __forceinline__ void cp16(uint32_t dst, const void* src) {
    asm volatile("cp.async.cg.shared.global [%0], [%1], 16;" :: "r"(dst), "l"(src));
}
#define CP_COMMIT() asm volatile("cp.async.commit_group;" ::: "memory")
#define CP_WAIT1()  asm volatile("cp.async.wait_group 1;" ::: "memory")
#define CP_WAIT0()  asm volatile("cp.async.wait_group 0;" ::: "memory")
#define SWZ128(b) ((b) ^ (((b) >> 3) & 0x70))

#define LDSM_X4(r, addr) \
    asm volatile("ldmatrix.sync.aligned.m8n8.x4.shared.b16 {%0,%1,%2,%3}, [%4];" \
        : "=r"((r)[0]), "=r"((r)[1]), "=r"((r)[2]), "=r"((r)[3]) : "r"(addr))

__device__ __forceinline__ void mma16816(float* c, const uint32_t* a, const uint32_t* b) {
    asm volatile(
        "mma.sync.aligned.m16n8k16.row.col.f32.bf16.bf16.f32 "
        "{%0,%1,%2,%3},{%4,%5,%6,%7},{%8,%9},{%0,%1,%2,%3};"
        : "+f"(c[0]), "+f"(c[1]), "+f"(c[2]), "+f"(c[3])
        : "r"(a[0]), "r"(a[1]), "r"(a[2]), "r"(a[3]), "r"(b[0]), "r"(b[1]));
}

__device__ __forceinline__ float warpReduceSum(float v) {
#pragma unroll
    for (int o = 16; o; o >>= 1) v += __shfl_xor_sync(0xffffffffu, v, o);
    return v;
}
__device__ __forceinline__ float warpReduceMax(float v) {
#pragma unroll
    for (int o = 16; o; o >>= 1) v = fmaxf(v, __shfl_xor_sync(0xffffffffu, v, o));
    return v;
}

// ---------------- rmsnorm + silu + bf16 split ----------------
__global__ __launch_bounds__(128) void rmsnorm_split(
    const float* __restrict__ x, const float* __restrict__ g,
    bf16* __restrict__ hi, bf16* __restrict__ lo, int do_silu)
{
    __shared__ float red[4];
    const int r = blockIdx.x, tid = threadIdx.x;
    const float4 v = *(const float4*)(x + (size_t)r * CCH + tid * 4);
    float ss = v.x*v.x + v.y*v.y + v.z*v.z + v.w*v.w;
    ss = warpReduceSum(ss);
    if ((tid & 31) == 0) red[tid >> 5] = ss;
    __syncthreads();
    const float tot = red[0] + red[1] + red[2] + red[3];
    const float scale = 22.62741699796952f / (sqrtf(tot) + 1e-8f);
    const float4 gg = *(const float4*)(g + tid * 4);
    float o[4];
    o[0] = v.x*scale*gg.x; o[1] = v.y*scale*gg.y; o[2] = v.z*scale*gg.z; o[3] = v.w*scale*gg.w;
    if (do_silu) {
#pragma unroll
        for (int i = 0; i < 4; i++) o[i] = o[i] / (1.0f + __expf(-o[i]));
    }
    const size_t base = (size_t)r * CCH + tid * 4;
#pragma unroll
    for (int i = 0; i < 4; i++) {
        bf16 h = __float2bfloat16(o[i]);
        hi[base + i] = h;
        lo[base + i] = __float2bfloat16(o[i] - __bfloat162float(h));
    }
}

// ---------------- plain bf16 split ----------------
__global__ __launch_bounds__(256) void split4_kernel(
    const float* __restrict__ in, bf16* __restrict__ hi, bf16* __restrict__ lo, int n4)
{
    const int i = blockIdx.x * 256 + threadIdx.x;
    if (i >= n4) return;
    const float4 v = ((const float4*)in)[i];
    float o[4] = {v.x, v.y, v.z, v.w};
    const size_t base = (size_t)i * 4;
#pragma unroll
    for (int j = 0; j < 4; j++) {
        bf16 h = __float2bfloat16(o[j]);
        hi[base + j] = h;
        lo[base + j] = __float2bfloat16(o[j] - __bfloat162float(h));
    }
}

// ---------------- transpose + split ----------------
__global__ void transpose_split(
    const float* __restrict__ in, bf16* __restrict__ hi, bf16* __restrict__ lo, int R, int Cc)
{
    __shared__ float t[32][33];
    const int c0 = blockIdx.x * 32, r0 = blockIdx.y * 32;
    const int tx = threadIdx.x;
    for (int j = threadIdx.y; j < 32; j += 8)
        t[j][tx] = in[(size_t)(r0 + j) * Cc + c0 + tx];
    __syncthreads();
    for (int j = threadIdx.y; j < 32; j += 8) {
        float v = t[tx][j];
        bf16 h = __float2bfloat16(v);
        const size_t o = (size_t)(c0 + j) * R + r0 + tx;
        hi[o] = h;
        lo[o] = __float2bfloat16(v - __bfloat162float(h));
    }
}

// ---------------- softmax -> bf16 split probs ----------------
__global__ __launch_bounds__(256) void softmax_split(
    const float* __restrict__ S, bf16* __restrict__ PHi, bf16* __restrict__ PLo)
{
    __shared__ float red[8];
    const int r = blockIdx.x, tid = threadIdx.x;
    const int cnt = (((r >> 10) + 1) << 10) >> 8;
    const float* row = S + (size_t)r * SPOS;

    float vals[32];
    float mx = -3.4e38f;
#pragma unroll
    for (int i = 0; i < 32; i++)
        if (i < cnt) { vals[i] = row[i * 256 + tid]; mx = fmaxf(mx, vals[i]); }
    mx = warpReduceMax(mx);
    if ((tid & 31) == 0) red[tid >> 5] = mx;
    __syncthreads();
    float m2 = red[0];
#pragma unroll
    for (int i = 1; i < 8; i++) m2 = fmaxf(m2, red[i]);
    __syncthreads();
    float sum = 0.0f;
#pragma unroll
    for (int i = 0; i < 32; i++)
        if (i < cnt) { vals[i] = __expf(vals[i] - m2); sum += vals[i]; }
    sum = warpReduceSum(sum);
    if ((tid & 31) == 0) red[tid >> 5] = sum;
    __syncthreads();
    float tot = 0.0f;
#pragma unroll
    for (int i = 0; i < 8; i++) tot += red[i];
    const float inv = 1.0f / tot;
    bf16* ph = PHi + (size_t)r * SPOS;
    bf16* pl = PLo + (size_t)r * SPOS;
#pragma unroll
    for (int i = 0; i < 32; i++)
        if (i < cnt) {
            float p = vals[i] * inv;
            bf16 h = __float2bfloat16(p);
            ph[i * 256 + tid] = h;
            pl[i * 256 + tid] = __float2bfloat16(p - __bfloat162float(h));
        }
}

// ---------------- HMMA split-bf16 GEMM ----------------
// C[M,N](fp32) = A[M,K] * B[N,K]^T, A/B bf16 hi/lo pairs (K contiguous).
#define TCG_GATHER 1
#define TCG_VARK   2
#define TCG_CAUSAL 4

__global__ __launch_bounds__(256) void tc_gemm(
    const bf16* __restrict__ AHi, const bf16* __restrict__ ALo, int ldA,
    const bf16* __restrict__ BHi, const bf16* __restrict__ BLo, int ldB,
    const float* __restrict__ bias, const float* __restrict__ resid,
    float* __restrict__ C, int ldc, int Ktot, int flags, float scale)
{
    extern __shared__ char smem[];
    const int m0 = blockIdx.y * 128, n0 = blockIdx.x * 128;
    if (flags & TCG_CAUSAL) { if (n0 >= (((m0 >> 10) + 1) << 10)) return; }
    if (flags & TCG_VARK)   { Ktot = ((m0 >> 10) + 1) << 10; }

    const uint32_t sb = smem_u32(smem);
    const uint32_t tbase = (sb + 1023) & ~1023u;         // 1024-aligned tile region
    char* tiles = smem + (tbase - sb);
    int* sBase = (int*)(tiles + 131072);

    const int tid = threadIdx.x, wid = tid >> 5, lid = tid & 31;
    const int wm = wid >> 2, wn = wid & 3;               // warp tile: 64x32
    const bool gather = (flags & TCG_GATHER);

    if (gather) {
        for (int i = tid; i < 128 * 27; i += 256) {
            const int mloc = i / 27, tap = i - mloc * 27;
            const int m = m0 + mloc;
            const int kt = tap / 9, r9 = tap - kt * 9, kh = r9 / 3, kw = r9 - kh * 3;
            const int t = m >> 10, hw = m & 1023, h = hw >> 5, w = hw & 31;
            int tin = t + kt - 2; tin = tin < 0 ? 0 : tin;
            int hin = h + kh - 1; hin = hin < 0 ? 0 : (hin > 31 ? 31 : hin);
            int win = w + kw - 1; win = win < 0 ? 0 : (win > 31 ? 31 : win);
            sBase[i] = ((tin << 10) + (hin << 5) + win) << 9;
        }
        __syncthreads();
    }

    // loader: 1024 16B-chunks per matrix, 4 per thread
    const int lrow = tid >> 1;                     // base row pairings below
    (void)lrow;

    auto load_chunk = [&](int c, int buf) {
        const uint32_t tbu = tbase + buf * 65536;
        const long kkB = (long)c << 6;
        const int tap = c >> 3, c0 = (c & 7) << 6;
#pragma unroll
        for (int it = 0; it < 4; it++) {
            const int i = it * 256 + tid;
            const int row = i >> 3, seg = i & 7;
            long offA;
            if (gather) offA = (long)sBase[row * 27 + tap] + c0 + (seg << 3);
            else        offA = (long)(m0 + row) * ldA + kkB + (seg << 3);
            const long offB = (long)(n0 + row) * ldB + kkB + (seg << 3);
            const uint32_t d = SWZ128((uint32_t)(row * 128 + seg * 16));
            cp16(tbu + d,         AHi + offA);
            cp16(tbu + 16384 + d, ALo + offA);
            cp16(tbu + 32768 + d, BHi + offB);
            cp16(tbu + 49152 + d, BLo + offB);
        }
    };

    float acc[4][4][4];
#pragma unroll
    for (int a = 0; a < 4; a++)
#pragma unroll
        for (int b = 0; b < 4; b++)
#pragma unroll
            for (int i = 0; i < 4; i++) acc[a][b][i] = 0.0f;

    // per-lane ldmatrix row/koffset components
    const int a_r = lid & 15, a_ko = (lid >> 4) * 16;              // A x4
    const int b_r = ((lid >> 4) << 3) + (lid & 7);                 // B x4 (2 n-tiles)
    const int b_ko = ((lid >> 3) & 1) * 16;

    const int nc = Ktot >> 6;
    load_chunk(0, 0);
    CP_COMMIT();

    for (int c = 0; c < nc; c++) {
        if (c + 1 < nc) { load_chunk(c + 1, (c + 1) & 1); CP_COMMIT(); CP_WAIT1(); }
        else            { CP_WAIT0(); }
        __syncthreads();

        const uint32_t tbu = tbase + (c & 1) * 65536;
#pragma unroll
        for (int ks = 0; ks < 4; ks++) {
            const int kb = ks * 32;
            uint32_t ah[4][4], al[4][4];
#pragma unroll
            for (int mt = 0; mt < 4; mt++) {
                const int row = wm * 64 + mt * 16 + a_r;
                const uint32_t off = SWZ128((uint32_t)(row * 128 + kb + a_ko));
                LDSM_X4(ah[mt], tbu + off);
                LDSM_X4(al[mt], tbu + 16384 + off);
            }
            uint32_t bh[4][2], bl[4][2];
#pragma unroll
            for (int p = 0; p < 2; p++) {
                const int row = wn * 32 + p * 16 + b_r;
                const uint32_t off = SWZ128((uint32_t)(row * 128 + kb + b_ko));
                uint32_t r4[4];
                LDSM_X4(r4, tbu + 32768 + off);
                bh[2*p][0] = r4[0]; bh[2*p][1] = r4[1];
                bh[2*p+1][0] = r4[2]; bh[2*p+1][1] = r4[3];
                LDSM_X4(r4, tbu + 49152 + off);
                bl[2*p][0] = r4[0]; bl[2*p][1] = r4[1];
                bl[2*p+1][0] = r4[2]; bl[2*p+1][1] = r4[3];
            }
#pragma unroll
            for (int mt = 0; mt < 4; mt++)
#pragma unroll
                for (int nt = 0; nt < 4; nt++) {
                    mma16816(acc[mt][nt], ah[mt], bh[nt]);
                    mma16816(acc[mt][nt], ah[mt], bl[nt]);
                    mma16816(acc[mt][nt], al[mt], bh[nt]);
                }
        }
        __syncthreads();
    }

    // epilogue: fragment layout c0,c1 -> row lid>>2, cols (lid&3)*2; c2,c3 -> row+8
    const int er = lid >> 2, ec = (lid & 3) * 2;
#pragma unroll
    for (int mt = 0; mt < 4; mt++) {
#pragma unroll
        for (int nt = 0; nt < 4; nt++) {
            const int n = n0 + wn * 32 + nt * 8 + ec;
            float b0 = 0.f, b1 = 0.f;
            if (bias) { b0 = bias[n]; b1 = bias[n + 1]; }
#pragma unroll
            for (int half = 0; half < 2; half++) {
                const int m = m0 + wm * 64 + mt * 16 + er + half * 8;
                float v0 = acc[mt][nt][half * 2 + 0] * scale + b0;
                float v1 = acc[mt][nt][half * 2 + 1] * scale + b1;
                if (resid) {
                    const float2 rv = *(const float2*)(resid + (size_t)m * ldc + n);
                    v0 += rv.x; v1 += rv.y;
                }
                *(float2*)(C + (size_t)m * ldc + n) = make_float2(v0, v1);
            }
        }
    }
}

// ---------------- host orchestration ----------------
extern "C" void kernel_launch(void* const* d_in, const int* in_sizes, int n_in,
                              void* d_out, int out_size)
{
    const float* x    = (const float*)d_in[0];
    const float* r1g1 = (const float*)d_in[1];
    const float* r1w1 = (const float*)d_in[2];
    const float* r1b1 = (const float*)d_in[3];
    const float* r1g2 = (const float*)d_in[4];
    const float* r1w2 = (const float*)d_in[5];
    const float* r1b2 = (const float*)d_in[6];
    const float* atg  = (const float*)d_in[7];
    const float* qw   = (const float*)d_in[8];
    const float* qb   = (const float*)d_in[9];
    const float* kw   = (const float*)d_in[10];
    const float* kb   = (const float*)d_in[11];
    const float* vw   = (const float*)d_in[12];
    const float* vb   = (const float*)d_in[13];
    const float* pw   = (const float*)d_in[14];
    const float* pb   = (const float*)d_in[15];
    const float* r2g1 = (const float*)d_in[16];
    const float* r2w1 = (const float*)d_in[17];
    const float* r2b1 = (const float*)d_in[18];
    const float* r2g2 = (const float*)d_in[19];
    const float* r2w2 = (const float*)d_in[20];
    const float* r2b2 = (const float*)d_in[21];
    float* out = (float*)d_out;

    bf16 *nHi, *nLo, *wHi, *wLo, *qHi, *qLo, *kHi, *kLo, *vtHi, *vtLo, *pHi, *pLo;
    float *s, *t, *h, *y;
    cudaGetSymbolAddress((void**)&nHi, g_nHi);  cudaGetSymbolAddress((void**)&nLo, g_nLo);
    cudaGetSymbolAddress((void**)&wHi, g_wHi);  cudaGetSymbolAddress((void**)&wLo, g_wLo);
    cudaGetSymbolAddress((void**)&qHi, g_qHi);  cudaGetSymbolAddress((void**)&qLo, g_qLo);
    cudaGetSymbolAddress((void**)&kHi, g_kHi);  cudaGetSymbolAddress((void**)&kLo, g_kLo);
    cudaGetSymbolAddress((void**)&vtHi, g_vtHi); cudaGetSymbolAddress((void**)&vtLo, g_vtLo);
    cudaGetSymbolAddress((void**)&pHi, g_pHi);  cudaGetSymbolAddress((void**)&pLo, g_pLo);
    cudaGetSymbolAddress((void**)&s, g_s);
    cudaGetSymbolAddress((void**)&t, g_t);
    cudaGetSymbolAddress((void**)&h, g_h);
    cudaGetSymbolAddress((void**)&y, g_y);

    const int SMB = 1024 + 131072 + 13824;   // pad + 2x64KB stages + tap table
    cudaFuncSetAttribute(tc_gemm, cudaFuncAttributeMaxDynamicSharedMemorySize, SMB);

    const dim3 gStd(4, 64);
    const dim3 gNT(64, 64);
    const dim3 tBlk(32, 8);
    const dim3 gWT3(16, 432);
    const dim3 gWT1(16, 16);
    const dim3 gVT(16, 256);
    const int n4 = SPOS * CCH / 4;
    const float rs512 = 0.04419417382415922f;

    // ---- resnet 1 ----
    rmsnorm_split<<<SPOS, 128>>>(x, r1g1, nHi, nLo, 1);
    transpose_split<<<gWT3, tBlk>>>(r1w1, wHi, wLo, CONVK, CCH);
    tc_gemm<<<gStd, 256, SMB>>>(nHi, nLo, CCH, wHi, wLo, CONVK, r1b1, nullptr, h, CCH, CONVK, TCG_GATHER, 1.0f);
    rmsnorm_split<<<SPOS, 128>>>(h, r1g2, nHi, nLo, 1);
    transpose_split<<<gWT3, tBlk>>>(r1w2, wHi, wLo, CONVK, CCH);
    tc_gemm<<<gStd, 256, SMB>>>(nHi, nLo, CCH, wHi, wLo, CONVK, r1b2, x, y, CCH, CONVK, TCG_GATHER, 1.0f);

    // ---- attention ----
    rmsnorm_split<<<SPOS, 128>>>(y, atg, nHi, nLo, 0);
    transpose_split<<<gWT1, tBlk>>>(qw, wHi, wLo, CCH, CCH);
    tc_gemm<<<gStd, 256, SMB>>>(nHi, nLo, CCH, wHi, wLo, CCH, qb, nullptr, t, CCH, CCH, 0, 1.0f);
    split4_kernel<<<n4 / 256, 256>>>(t, qHi, qLo, n4);
    transpose_split<<<gWT1, tBlk>>>(kw, wHi, wLo, CCH, CCH);
    tc_gemm<<<gStd, 256, SMB>>>(nHi, nLo, CCH, wHi, wLo, CCH, kb, nullptr, t, CCH, CCH, 0, 1.0f);
    split4_kernel<<<n4 / 256, 256>>>(t, kHi, kLo, n4);
    transpose_split<<<gWT1, tBlk>>>(vw, wHi, wLo, CCH, CCH);
    tc_gemm<<<gStd, 256, SMB>>>(nHi, nLo, CCH, wHi, wLo, CCH, vb, nullptr, t, CCH, CCH, 0, 1.0f);
    transpose_split<<<gVT, tBlk>>>(t, vtHi, vtLo, SPOS, CCH);

    tc_gemm<<<gNT, 256, SMB>>>(qHi, qLo, CCH, kHi, kLo, CCH, nullptr, nullptr, s, SPOS, CCH, TCG_CAUSAL, rs512);
    softmax_split<<<SPOS, 256>>>(s, pHi, pLo);
    tc_gemm<<<gStd, 256, SMB>>>(pHi, pLo, SPOS, vtHi, vtLo, SPOS, nullptr, nullptr, t, CCH, SPOS, TCG_VARK, 1.0f);
    split4_kernel<<<n4 / 256, 256>>>(t, qHi, qLo, n4);
    transpose_split<<<gWT1, tBlk>>>(pw, wHi, wLo, CCH, CCH);
    tc_gemm<<<gStd, 256, SMB>>>(qHi, qLo, CCH, wHi, wLo, CCH, pb, y, h, CCH, CCH, 0, 1.0f);

    // ---- resnet 2 ----
    rmsnorm_split<<<SPOS, 128>>>(h, r2g1, nHi, nLo, 1);
    transpose_split<<<gWT3, tBlk>>>(r2w1, wHi, wLo, CONVK, CCH);
    tc_gemm<<<gStd, 256, SMB>>>(nHi, nLo, CCH, wHi, wLo, CONVK, r2b1, nullptr, t, CCH, CONVK, TCG_GATHER, 1.0f);
    rmsnorm_split<<<SPOS, 128>>>(t, r2g2, nHi, nLo, 1);
    transpose_split<<<gWT3, tBlk>>>(r2w2, wHi, wLo, CONVK, CCH);
    tc_gemm<<<gStd, 256, SMB>>>(nHi, nLo, CCH, wHi, wLo, CONVK, r2b2, h, out, CCH, CONVK, TCG_GATHER, 1.0f);
}

// round 4
// speedup vs baseline: 3.1956x; 1.0688x over previous
#include <cuda_runtime.h>
#include <cuda_bf16.h>
#include <cstdint>
#include <math.h>

#define SPOS 8192
#define CCH  512
#define CONVK 13824   // 27*512

typedef __nv_bfloat16 bf16;

// ---------------- scratch (static device memory) ----------------
__device__ __align__(256) bf16 g_nHi[SPOS*CCH], g_nLo[SPOS*CCH];
__device__ __align__(256) bf16 g_wHi[CONVK*CCH], g_wLo[CONVK*CCH];
__device__ __align__(256) bf16 g_qHi[SPOS*CCH], g_qLo[SPOS*CCH];
__device__ __align__(256) bf16 g_kHi[SPOS*CCH], g_kLo[SPOS*CCH];
__device__ __align__(256) bf16 g_vtHi[SPOS*CCH], g_vtLo[SPOS*CCH];
__device__ __align__(256) bf16 g_pHi[(size_t)SPOS*SPOS], g_pLo[(size_t)SPOS*SPOS];
__device__ __align__(256) float g_s[(size_t)SPOS*SPOS];
__device__ __align__(256) float g_t[SPOS*CCH], g_h[SPOS*CCH], g_y[SPOS*CCH];

// ---------------- helpers ----------------
__device__ __forceinline__ uint32_t smem_u32(const void* p) {
    uint32_t a;
    asm("{ .reg .u64 t; cvta.to.shared.u64 t, %1; cvt.u32.u64 %0, t; }" : "=r"(a) : "l"(p));
    return a;
}
__device__ __forceinline__ void cp16(uint32_t dst, const void* src) {
    asm volatile("cp.async.cg.shared.global [%0], [%1], 16;" :: "r"(dst), "l"(src));
}
#define CP_COMMIT() asm volatile("cp.async.commit_group;" ::: "memory")
#define CP_WAIT1()  asm volatile("cp.async.wait_group 1;" ::: "memory")
#define CP_WAIT0()  asm volatile("cp.async.wait_group 0;" ::: "memory")
#define SWZ128(b) ((b) ^ (((b) >> 3) & 0x70))

#define LDSM_X4(r, addr) \
    asm volatile("ldmatrix.sync.aligned.m8n8.x4.shared.b16 {%0,%1,%2,%3}, [%4];" \
        : "=r"((r)[0]), "=r"((r)[1]), "=r"((r)[2]), "=r"((r)[3]) : "r"(addr))

__device__ __forceinline__ void mma16816(float* c, const uint32_t* a, const uint32_t* b) {
    asm volatile(
        "mma.sync.aligned.m16n8k16.row.col.f32.bf16.bf16.f32 "
        "{%0,%1,%2,%3},{%4,%5,%6,%7},{%8,%9},{%0,%1,%2,%3};"
        : "+f"(c[0]), "+f"(c[1]), "+f"(c[2]), "+f"(c[3])
        : "r"(a[0]), "r"(a[1]), "r"(a[2]), "r"(a[3]), "r"(b[0]), "r"(b[1]));
}

__device__ __forceinline__ float warpReduceSum(float v) {
#pragma unroll
    for (int o = 16; o; o >>= 1) v += __shfl_xor_sync(0xffffffffu, v, o);
    return v;
}
__device__ __forceinline__ float warpReduceMax(float v) {
#pragma unroll
    for (int o = 16; o; o >>= 1) v = fmaxf(v, __shfl_xor_sync(0xffffffffu, v, o));
    return v;
}

// ---------------- rmsnorm + silu + bf16 split ----------------
__global__ __launch_bounds__(128) void rmsnorm_split(
    const float* __restrict__ x, const float* __restrict__ g,
    bf16* __restrict__ hi, bf16* __restrict__ lo, int do_silu)
{
    __shared__ float red[4];
    const int r = blockIdx.x, tid = threadIdx.x;
    const float4 v = *(const float4*)(x + (size_t)r * CCH + tid * 4);
    float ss = v.x*v.x + v.y*v.y + v.z*v.z + v.w*v.w;
    ss = warpReduceSum(ss);
    if ((tid & 31) == 0) red[tid >> 5] = ss;
    __syncthreads();
    const float tot = red[0] + red[1] + red[2] + red[3];
    const float scale = 22.62741699796952f / (sqrtf(tot) + 1e-8f);
    const float4 gg = *(const float4*)(g + tid * 4);
    float o[4];
    o[0] = v.x*scale*gg.x; o[1] = v.y*scale*gg.y; o[2] = v.z*scale*gg.z; o[3] = v.w*scale*gg.w;
    if (do_silu) {
#pragma unroll
        for (int i = 0; i < 4; i++) o[i] = o[i] / (1.0f + __expf(-o[i]));
    }
    const size_t base = (size_t)r * CCH + tid * 4;
#pragma unroll
    for (int i = 0; i < 4; i++) {
        bf16 h = __float2bfloat16(o[i]);
        hi[base + i] = h;
        lo[base + i] = __float2bfloat16(o[i] - __bfloat162float(h));
    }
}

// ---------------- transpose + split ----------------
__global__ void transpose_split(
    const float* __restrict__ in, bf16* __restrict__ hi, bf16* __restrict__ lo, int R, int Cc)
{
    __shared__ float t[32][33];
    const int c0 = blockIdx.x * 32, r0 = blockIdx.y * 32;
    const int tx = threadIdx.x;
    for (int j = threadIdx.y; j < 32; j += 8)
        t[j][tx] = in[(size_t)(r0 + j) * Cc + c0 + tx];
    __syncthreads();
    for (int j = threadIdx.y; j < 32; j += 8) {
        float v = t[tx][j];
        bf16 h = __float2bfloat16(v);
        const size_t o = (size_t)(c0 + j) * R + r0 + tx;
        hi[o] = h;
        lo[o] = __float2bfloat16(v - __bfloat162float(h));
    }
}

// ---------------- softmax -> bf16 split probs ----------------
__global__ __launch_bounds__(256) void softmax_split(
    const float* __restrict__ S, bf16* __restrict__ PHi, bf16* __restrict__ PLo)
{
    __shared__ float red[8];
    const int r = blockIdx.x, tid = threadIdx.x;
    const int cnt = (((r >> 10) + 1) << 10) >> 8;
    const float* row = S + (size_t)r * SPOS;

    float vals[32];
    float mx = -3.4e38f;
#pragma unroll
    for (int i = 0; i < 32; i++)
        if (i < cnt) { vals[i] = row[i * 256 + tid]; mx = fmaxf(mx, vals[i]); }
    mx = warpReduceMax(mx);
    if ((tid & 31) == 0) red[tid >> 5] = mx;
    __syncthreads();
    float m2 = red[0];
#pragma unroll
    for (int i = 1; i < 8; i++) m2 = fmaxf(m2, red[i]);
    __syncthreads();
    float sum = 0.0f;
#pragma unroll
    for (int i = 0; i < 32; i++)
        if (i < cnt) { vals[i] = __expf(vals[i] - m2); sum += vals[i]; }
    sum = warpReduceSum(sum);
    if ((tid & 31) == 0) red[tid >> 5] = sum;
    __syncthreads();
    float tot = 0.0f;
#pragma unroll
    for (int i = 0; i < 8; i++) tot += red[i];
    const float inv = 1.0f / tot;
    bf16* ph = PHi + (size_t)r * SPOS;
    bf16* pl = PLo + (size_t)r * SPOS;
#pragma unroll
    for (int i = 0; i < 32; i++)
        if (i < cnt) {
            float p = vals[i] * inv;
            bf16 h = __float2bfloat16(p);
            ph[i * 256 + tid] = h;
            pl[i * 256 + tid] = __float2bfloat16(p - __bfloat162float(h));
        }
}

// ---------------- HMMA split-bf16 GEMM, CTA tile 128x256, warp tile 64x64 ----------------
#define TCG_GATHER 1
#define TCG_VARK   2
#define TCG_CAUSAL 4

#define STAGE 98304  // 96KB: Ahi 16K, Alo 16K, Bhi 32K, Blo 32K

__global__ __launch_bounds__(256) void tc_gemm(
    const bf16* __restrict__ AHi, const bf16* __restrict__ ALo, int ldA,
    const bf16* __restrict__ BHi, const bf16* __restrict__ BLo, int ldB,
    const float* __restrict__ bias, const float* __restrict__ resid,
    float* __restrict__ C, bf16* __restrict__ outHi, bf16* __restrict__ outLo,
    int ldc, int Ktot, int flags, float scale)
{
    extern __shared__ char smem[];
    const int m0 = blockIdx.y * 128, n0 = blockIdx.x * 256;
    if (flags & TCG_CAUSAL) { if (n0 >= (((m0 >> 10) + 1) << 10)) return; }
    if (flags & TCG_VARK)   { Ktot = ((m0 >> 10) + 1) << 10; }

    const uint32_t sb = smem_u32(smem);
    const uint32_t tbase = (sb + 1023) & ~1023u;
    char* tiles = smem + (tbase - sb);
    int* sBase = (int*)(tiles + 2 * STAGE);

    const int tid = threadIdx.x, wid = tid >> 5, lid = tid & 31;
    const int wm = wid >> 2, wn = wid & 3;               // warp tile: 64x64
    const bool gather = (flags & TCG_GATHER);

    if (gather) {
        for (int i = tid; i < 128 * 27; i += 256) {
            const int mloc = i / 27, tap = i - mloc * 27;
            const int m = m0 + mloc;
            const int kt = tap / 9, r9 = tap - kt * 9, kh = r9 / 3, kw = r9 - kh * 3;
            const int t = m >> 10, hw = m & 1023, h = hw >> 5, w = hw & 31;
            int tin = t + kt - 2; tin = tin < 0 ? 0 : tin;
            int hin = h + kh - 1; hin = hin < 0 ? 0 : (hin > 31 ? 31 : hin);
            int win = w + kw - 1; win = win < 0 ? 0 : (win > 31 ? 31 : win);
            sBase[i] = ((tin << 10) + (hin << 5) + win) << 9;
        }
        __syncthreads();
    }

    auto load_chunk = [&](int c, int buf) {
        const uint32_t tbu = tbase + buf * STAGE;
        const long kkB = (long)c << 6;
        const int tap = c >> 3, c0 = (c & 7) << 6;
#pragma unroll
        for (int it = 0; it < 4; it++) {          // A: 128 rows x 8 segs
            const int i = it * 256 + tid;
            const int row = i >> 3, seg = i & 7;
            long offA;
            if (gather) offA = (long)sBase[row * 27 + tap] + c0 + (seg << 3);
            else        offA = (long)(m0 + row) * ldA + kkB + (seg << 3);
            const uint32_t d = SWZ128((uint32_t)(row * 128 + seg * 16));
            cp16(tbu + d,         AHi + offA);
            cp16(tbu + 16384 + d, ALo + offA);
        }
#pragma unroll
        for (int it = 0; it < 8; it++) {          // B: 256 rows x 8 segs
            const int i = it * 256 + tid;
            const int row = i >> 3, seg = i & 7;
            const long offB = (long)(n0 + row) * ldB + kkB + (seg << 3);
            const uint32_t d = SWZ128((uint32_t)(row * 128 + seg * 16));
            cp16(tbu + 32768 + d, BHi + offB);
            cp16(tbu + 65536 + d, BLo + offB);
        }
    };

    float acc[4][8][4];
#pragma unroll
    for (int a = 0; a < 4; a++)
#pragma unroll
        for (int b = 0; b < 8; b++)
#pragma unroll
            for (int i = 0; i < 4; i++) acc[a][b][i] = 0.0f;

    const int a_r = lid & 15, a_ko = (lid >> 4) * 16;
    const int b_r = ((lid >> 4) << 3) + (lid & 7);
    const int b_ko = ((lid >> 3) & 1) * 16;

    const int nc = Ktot >> 6;
    load_chunk(0, 0);
    CP_COMMIT();

    for (int c = 0; c < nc; c++) {
        if (c + 1 < nc) { load_chunk(c + 1, (c + 1) & 1); CP_COMMIT(); CP_WAIT1(); }
        else            { CP_WAIT0(); }
        __syncthreads();

        const uint32_t tbu = tbase + (c & 1) * STAGE;
#pragma unroll
        for (int ks = 0; ks < 4; ks++) {
            const int kb = ks * 32;
            uint32_t ah[4][4], al[4][4];
#pragma unroll
            for (int mt = 0; mt < 4; mt++) {
                const int row = wm * 64 + mt * 16 + a_r;
                const uint32_t off = SWZ128((uint32_t)(row * 128 + kb + a_ko));
                LDSM_X4(ah[mt], tbu + off);
                LDSM_X4(al[mt], tbu + 16384 + off);
            }
#pragma unroll
            for (int p = 0; p < 4; p++) {
                const int row = wn * 64 + p * 16 + b_r;
                const uint32_t off = SWZ128((uint32_t)(row * 128 + kb + b_ko));
                uint32_t rh[4], rl[4];
                LDSM_X4(rh, tbu + 32768 + off);
                LDSM_X4(rl, tbu + 65536 + off);
#pragma unroll
                for (int mt = 0; mt < 4; mt++) {
                    mma16816(acc[mt][2*p],   ah[mt], rh);
                    mma16816(acc[mt][2*p],   ah[mt], rl);
                    mma16816(acc[mt][2*p],   al[mt], rh);
                    mma16816(acc[mt][2*p+1], ah[mt], rh + 2);
                    mma16816(acc[mt][2*p+1], ah[mt], rl + 2);
                    mma16816(acc[mt][2*p+1], al[mt], rh + 2);
                }
            }
        }
        __syncthreads();
    }

    // epilogue
    const int er = lid >> 2, ec = (lid & 3) * 2;
#pragma unroll
    for (int mt = 0; mt < 4; mt++) {
#pragma unroll
        for (int nt = 0; nt < 8; nt++) {
            const int n = n0 + wn * 64 + nt * 8 + ec;
            float b0 = 0.f, b1 = 0.f;
            if (bias) { b0 = bias[n]; b1 = bias[n + 1]; }
#pragma unroll
            for (int half = 0; half < 2; half++) {
                const int m = m0 + wm * 64 + mt * 16 + er + half * 8;
                float v0 = acc[mt][nt][half * 2 + 0] * scale + b0;
                float v1 = acc[mt][nt][half * 2 + 1] * scale + b1;
                if (resid) {
                    const float2 rv = *(const float2*)(resid + (size_t)m * ldc + n);
                    v0 += rv.x; v1 += rv.y;
                }
                if (C)
                    *(float2*)(C + (size_t)m * ldc + n) = make_float2(v0, v1);
                if (outHi) {
                    bf16 h0 = __float2bfloat16(v0), h1 = __float2bfloat16(v1);
                    __nv_bfloat162 hh; hh.x = h0; hh.y = h1;
                    __nv_bfloat162 ll;
                    ll.x = __float2bfloat16(v0 - __bfloat162float(h0));
                    ll.y = __float2bfloat16(v1 - __bfloat162float(h1));
                    *(__nv_bfloat162*)(outHi + (size_t)m * ldc + n) = hh;
                    *(__nv_bfloat162*)(outLo + (size_t)m * ldc + n) = ll;
                }
            }
        }
    }
}

// ---------------- host orchestration ----------------
extern "C" void kernel_launch(void* const* d_in, const int* in_sizes, int n_in,
                              void* d_out, int out_size)
{
    const float* x    = (const float*)d_in[0];
    const float* r1g1 = (const float*)d_in[1];
    const float* r1w1 = (const float*)d_in[2];
    const float* r1b1 = (const float*)d_in[3];
    const float* r1g2 = (const float*)d_in[4];
    const float* r1w2 = (const float*)d_in[5];
    const float* r1b2 = (const float*)d_in[6];
    const float* atg  = (const float*)d_in[7];
    const float* qw   = (const float*)d_in[8];
    const float* qb   = (const float*)d_in[9];
    const float* kw   = (const float*)d_in[10];
    const float* kb   = (const float*)d_in[11];
    const float* vw   = (const float*)d_in[12];
    const float* vb   = (const float*)d_in[13];
    const float* pw   = (const float*)d_in[14];
    const float* pb   = (const float*)d_in[15];
    const float* r2g1 = (const float*)d_in[16];
    const float* r2w1 = (const float*)d_in[17];
    const float* r2b1 = (const float*)d_in[18];
    const float* r2g2 = (const float*)d_in[19];
    const float* r2w2 = (const float*)d_in[20];
    const float* r2b2 = (const float*)d_in[21];
    float* out = (float*)d_out;

    bf16 *nHi, *nLo, *wHi, *wLo, *qHi, *qLo, *kHi, *kLo, *vtHi, *vtLo, *pHi, *pLo;
    float *s, *t, *h, *y;
    cudaGetSymbolAddress((void**)&nHi, g_nHi);  cudaGetSymbolAddress((void**)&nLo, g_nLo);
    cudaGetSymbolAddress((void**)&wHi, g_wHi);  cudaGetSymbolAddress((void**)&wLo, g_wLo);
    cudaGetSymbolAddress((void**)&qHi, g_qHi);  cudaGetSymbolAddress((void**)&qLo, g_qLo);
    cudaGetSymbolAddress((void**)&kHi, g_kHi);  cudaGetSymbolAddress((void**)&kLo, g_kLo);
    cudaGetSymbolAddress((void**)&vtHi, g_vtHi); cudaGetSymbolAddress((void**)&vtLo, g_vtLo);
    cudaGetSymbolAddress((void**)&pHi, g_pHi);  cudaGetSymbolAddress((void**)&pLo, g_pLo);
    cudaGetSymbolAddress((void**)&s, g_s);
    cudaGetSymbolAddress((void**)&t, g_t);
    cudaGetSymbolAddress((void**)&h, g_h);
    cudaGetSymbolAddress((void**)&y, g_y);

    const int SMB = 1024 + 2 * STAGE + 13824;
    cudaFuncSetAttribute(tc_gemm, cudaFuncAttributeMaxDynamicSharedMemorySize, SMB);

    const dim3 gStd(2, 64);            // N=512 -> 2 n-tiles of 256
    const dim3 gNT(32, 64);            // scores: N=8192 -> 32 n-tiles
    const dim3 tBlk(32, 8);
    const dim3 gWT3(16, 432);
    const dim3 gWT1(16, 16);
    const dim3 gVT(16, 256);
    const float rs512 = 0.04419417382415922f;

    // ---- resnet 1 ----
    rmsnorm_split<<<SPOS, 128>>>(x, r1g1, nHi, nLo, 1);
    transpose_split<<<gWT3, tBlk>>>(r1w1, wHi, wLo, CONVK, CCH);
    tc_gemm<<<gStd, 256, SMB>>>(nHi, nLo, CCH, wHi, wLo, CONVK, r1b1, nullptr, h, nullptr, nullptr, CCH, CONVK, TCG_GATHER, 1.0f);
    rmsnorm_split<<<SPOS, 128>>>(h, r1g2, nHi, nLo, 1);
    transpose_split<<<gWT3, tBlk>>>(r1w2, wHi, wLo, CONVK, CCH);
    tc_gemm<<<gStd, 256, SMB>>>(nHi, nLo, CCH, wHi, wLo, CONVK, r1b2, x, y, nullptr, nullptr, CCH, CONVK, TCG_GATHER, 1.0f);

    // ---- attention ----
    rmsnorm_split<<<SPOS, 128>>>(y, atg, nHi, nLo, 0);
    transpose_split<<<gWT1, tBlk>>>(qw, wHi, wLo, CCH, CCH);
    tc_gemm<<<gStd, 256, SMB>>>(nHi, nLo, CCH, wHi, wLo, CCH, qb, nullptr, nullptr, qHi, qLo, CCH, CCH, 0, 1.0f);
    transpose_split<<<gWT1, tBlk>>>(kw, wHi, wLo, CCH, CCH);
    tc_gemm<<<gStd, 256, SMB>>>(nHi, nLo, CCH, wHi, wLo, CCH, kb, nullptr, nullptr, kHi, kLo, CCH, CCH, 0, 1.0f);
    transpose_split<<<gWT1, tBlk>>>(vw, wHi, wLo, CCH, CCH);
    tc_gemm<<<gStd, 256, SMB>>>(nHi, nLo, CCH, wHi, wLo, CCH, vb, nullptr, t, nullptr, nullptr, CCH, CCH, 0, 1.0f);
    transpose_split<<<gVT, tBlk>>>(t, vtHi, vtLo, SPOS, CCH);

    tc_gemm<<<gNT, 256, SMB>>>(qHi, qLo, CCH, kHi, kLo, CCH, nullptr, nullptr, s, nullptr, nullptr, SPOS, CCH, TCG_CAUSAL, rs512);
    softmax_split<<<SPOS, 256>>>(s, pHi, pLo);
    tc_gemm<<<gStd, 256, SMB>>>(pHi, pLo, SPOS, vtHi, vtLo, SPOS, nullptr, nullptr, nullptr, qHi, qLo, CCH, SPOS, TCG_VARK, 1.0f);
    transpose_split<<<gWT1, tBlk>>>(pw, wHi, wLo, CCH, CCH);
    tc_gemm<<<gStd, 256, SMB>>>(qHi, qLo, CCH, wHi, wLo, CCH, pb, y, h, nullptr, nullptr, CCH, CCH, 0, 1.0f);

    // ---- resnet 2 ----
    rmsnorm_split<<<SPOS, 128>>>(h, r2g1, nHi, nLo, 1);
    transpose_split<<<gWT3, tBlk>>>(r2w1, wHi, wLo, CONVK, CCH);
    tc_gemm<<<gStd, 256, SMB>>>(nHi, nLo, CCH, wHi, wLo, CONVK, r2b1, nullptr, t, nullptr, nullptr, CCH, CONVK, TCG_GATHER, 1.0f);
    rmsnorm_split<<<SPOS, 128>>>(t, r2g2, nHi, nLo, 1);
    transpose_split<<<gWT3, tBlk>>>(r2w2, wHi, wLo, CONVK, CCH);
    tc_gemm<<<gStd, 256, SMB>>>(nHi, nLo, CCH, wHi, wLo, CONVK, r2b2, h, out, nullptr, nullptr, CCH, CONVK, TCG_GATHER, 1.0f);
}

// round 5
// speedup vs baseline: 3.2718x; 1.0238x over previous
#include <cuda_runtime.h>
#include <cuda_bf16.h>
#include <cstdint>
#include <math.h>

#define SPOS 8192
#define CCH  512
#define CONVK 13824   // 27*512

typedef __nv_bfloat16 bf16;

// ---------------- scratch (static device memory) ----------------
__device__ __align__(256) bf16 g_nHi[SPOS*CCH], g_nLo[SPOS*CCH];
__device__ __align__(256) bf16 g_wHi[CONVK*CCH], g_wLo[CONVK*CCH];
__device__ __align__(256) bf16 g_qHi[SPOS*CCH], g_qLo[SPOS*CCH];
__device__ __align__(256) bf16 g_kHi[SPOS*CCH], g_kLo[SPOS*CCH];
__device__ __align__(256) bf16 g_vtHi[SPOS*CCH], g_vtLo[SPOS*CCH];
__device__ __align__(256) bf16 g_pHi[(size_t)SPOS*SPOS], g_pLo[(size_t)SPOS*SPOS];
__device__ __align__(256) float g_s[(size_t)SPOS*SPOS];
__device__ __align__(256) float g_t[SPOS*CCH], g_h[SPOS*CCH], g_y[SPOS*CCH];

// ---------------- helpers ----------------
__device__ __forceinline__ uint32_t smem_u32(const void* p) {
    uint32_t a;
    asm("{ .reg .u64 t; cvta.to.shared.u64 t, %1; cvt.u32.u64 %0, t; }" : "=r"(a) : "l"(p));
    return a;
}
__device__ __forceinline__ void cp16(uint32_t dst, const void* src) {
    asm volatile("cp.async.cg.shared.global [%0], [%1], 16;" :: "r"(dst), "l"(src));
}
#define CP_COMMIT() asm volatile("cp.async.commit_group;" ::: "memory")
#define CP_WAIT1()  asm volatile("cp.async.wait_group 1;" ::: "memory")
#define CP_WAIT0()  asm volatile("cp.async.wait_group 0;" ::: "memory")
#define SWZ128(b) ((b) ^ (((b) >> 3) & 0x70))

#define LDSM_X4(r, addr) \
    asm volatile("ldmatrix.sync.aligned.m8n8.x4.shared.b16 {%0,%1,%2,%3}, [%4];" \
        : "=r"((r)[0]), "=r"((r)[1]), "=r"((r)[2]), "=r"((r)[3]) : "r"(addr))

__device__ __forceinline__ void mma16816(float* c, const uint32_t* a, const uint32_t* b) {
    asm volatile(
        "mma.sync.aligned.m16n8k16.row.col.f32.bf16.bf16.f32 "
        "{%0,%1,%2,%3},{%4,%5,%6,%7},{%8,%9},{%0,%1,%2,%3};"
        : "+f"(c[0]), "+f"(c[1]), "+f"(c[2]), "+f"(c[3])
        : "r"(a[0]), "r"(a[1]), "r"(a[2]), "r"(a[3]), "r"(b[0]), "r"(b[1]));
}

__device__ __forceinline__ float warpReduceSum(float v) {
#pragma unroll
    for (int o = 16; o; o >>= 1) v += __shfl_xor_sync(0xffffffffu, v, o);
    return v;
}
__device__ __forceinline__ float warpReduceMax(float v) {
#pragma unroll
    for (int o = 16; o; o >>= 1) v = fmaxf(v, __shfl_xor_sync(0xffffffffu, v, o));
    return v;
}

// ---------------- rmsnorm + silu + bf16 split ----------------
__global__ __launch_bounds__(128) void rmsnorm_split(
    const float* __restrict__ x, const float* __restrict__ g,
    bf16* __restrict__ hi, bf16* __restrict__ lo, int do_silu)
{
    __shared__ float red[4];
    const int r = blockIdx.x, tid = threadIdx.x;
    const float4 v = *(const float4*)(x + (size_t)r * CCH + tid * 4);
    float ss = v.x*v.x + v.y*v.y + v.z*v.z + v.w*v.w;
    ss = warpReduceSum(ss);
    if ((tid & 31) == 0) red[tid >> 5] = ss;
    __syncthreads();
    const float tot = red[0] + red[1] + red[2] + red[3];
    const float scale = 22.62741699796952f / (sqrtf(tot) + 1e-8f);
    const float4 gg = *(const float4*)(g + tid * 4);
    float o[4];
    o[0] = v.x*scale*gg.x; o[1] = v.y*scale*gg.y; o[2] = v.z*scale*gg.z; o[3] = v.w*scale*gg.w;
    if (do_silu) {
#pragma unroll
        for (int i = 0; i < 4; i++) o[i] = o[i] / (1.0f + __expf(-o[i]));
    }
    const size_t base = (size_t)r * CCH + tid * 4;
#pragma unroll
    for (int i = 0; i < 4; i++) {
        bf16 h = __float2bfloat16(o[i]);
        hi[base + i] = h;
        lo[base + i] = __float2bfloat16(o[i] - __bfloat162float(h));
    }
}

// ---------------- transpose + split ----------------
__global__ void transpose_split(
    const float* __restrict__ in, bf16* __restrict__ hi, bf16* __restrict__ lo, int R, int Cc)
{
    __shared__ float t[32][33];
    const int c0 = blockIdx.x * 32, r0 = blockIdx.y * 32;
    const int tx = threadIdx.x;
    for (int j = threadIdx.y; j < 32; j += 8)
        t[j][tx] = in[(size_t)(r0 + j) * Cc + c0 + tx];
    __syncthreads();
    for (int j = threadIdx.y; j < 32; j += 8) {
        float v = t[tx][j];
        bf16 h = __float2bfloat16(v);
        const size_t o = (size_t)(c0 + j) * R + r0 + tx;
        hi[o] = h;
        lo[o] = __float2bfloat16(v - __bfloat162float(h));
    }
}

// ---------------- softmax -> bf16 split probs ----------------
__global__ __launch_bounds__(256) void softmax_split(
    const float* __restrict__ S, bf16* __restrict__ PHi, bf16* __restrict__ PLo)
{
    __shared__ float red[8];
    const int r = blockIdx.x, tid = threadIdx.x;
    const int cnt = (((r >> 10) + 1) << 10) >> 8;
    const float* row = S + (size_t)r * SPOS;

    float vals[32];
    float mx = -3.4e38f;
#pragma unroll
    for (int i = 0; i < 32; i++)
        if (i < cnt) { vals[i] = row[i * 256 + tid]; mx = fmaxf(mx, vals[i]); }
    mx = warpReduceMax(mx);
    if ((tid & 31) == 0) red[tid >> 5] = mx;
    __syncthreads();
    float m2 = red[0];
#pragma unroll
    for (int i = 1; i < 8; i++) m2 = fmaxf(m2, red[i]);
    __syncthreads();
    float sum = 0.0f;
#pragma unroll
    for (int i = 0; i < 32; i++)
        if (i < cnt) { vals[i] = __expf(vals[i] - m2); sum += vals[i]; }
    sum = warpReduceSum(sum);
    if ((tid & 31) == 0) red[tid >> 5] = sum;
    __syncthreads();
    float tot = 0.0f;
#pragma unroll
    for (int i = 0; i < 8; i++) tot += red[i];
    const float inv = 1.0f / tot;
    bf16* ph = PHi + (size_t)r * SPOS;
    bf16* pl = PLo + (size_t)r * SPOS;
#pragma unroll
    for (int i = 0; i < 32; i++)
        if (i < cnt) {
            float p = vals[i] * inv;
            bf16 h = __float2bfloat16(p);
            ph[i * 256 + tid] = h;
            pl[i * 256 + tid] = __float2bfloat16(p - __bfloat162float(h));
        }
}

// ---------------- HMMA split-bf16 GEMM, CTA tile BMx256, 512 threads ----------------
#define TCG_GATHER 1
#define TCG_VARK   2
#define TCG_CAUSAL 4

// BM=128: 16 warps as 2x8, warp tile 64x32.  BM=64: 16 warps as 1x16, warp tile 64x16.
template<int BM>
__global__ __launch_bounds__(512) void tc_gemm(
    const bf16* __restrict__ AHi, const bf16* __restrict__ ALo, int ldA,
    const bf16* __restrict__ BHi, const bf16* __restrict__ BLo, int ldB,
    const float* __restrict__ bias, const float* __restrict__ resid,
    float* __restrict__ C, bf16* __restrict__ outHi, bf16* __restrict__ outLo,
    int ldc, int Ktot, int flags, float scale)
{
    constexpr int WN = (BM == 128) ? 8 : 16;      // warps along n
    constexpr int NT = 32 / WN * 2 / 2;           // n-subtiles of 8: 4 or 2
    constexpr int NP = (BM == 128) ? 2 : 1;       // 16-row B groups per warp
    constexpr int WNW = 256 / WN;                 // warp n width: 32 or 16
    constexpr int ABYTES = BM * 128;              // A hi tile bytes
    constexpr int STAGEB = 2 * ABYTES + 65536;    // Ah+Al+Bh+Bl

    extern __shared__ char smem[];
    int mtile = blockIdx.y;
    if (flags & TCG_VARK) mtile = gridDim.y - 1 - blockIdx.y;   // descending-K order
    const int m0 = mtile * BM, n0 = blockIdx.x * 256;
    if (flags & TCG_CAUSAL) { if (n0 >= (((m0 >> 10) + 1) << 10)) return; }
    if (flags & TCG_VARK)   { Ktot = ((m0 >> 10) + 1) << 10; }

    const uint32_t sb = smem_u32(smem);
    const uint32_t tbase = (sb + 1023) & ~1023u;
    char* tiles = smem + (tbase - sb);
    int* sBase = (int*)(tiles + 2 * STAGEB);

    const int tid = threadIdx.x, wid = tid >> 5, lid = tid & 31;
    const int wm = wid / WN, wn = wid % WN;
    const bool gather = (flags & TCG_GATHER);

    if (gather) {
        for (int i = tid; i < BM * 27; i += 512) {
            const int mloc = i / 27, tap = i - mloc * 27;
            const int m = m0 + mloc;
            const int kt = tap / 9, r9 = tap - kt * 9, kh = r9 / 3, kw = r9 - kh * 3;
            const int t = m >> 10, hw = m & 1023, h = hw >> 5, w = hw & 31;
            int tin = t + kt - 2; tin = tin < 0 ? 0 : tin;
            int hin = h + kh - 1; hin = hin < 0 ? 0 : (hin > 31 ? 31 : hin);
            int win = w + kw - 1; win = win < 0 ? 0 : (win > 31 ? 31 : win);
            sBase[i] = ((tin << 10) + (hin << 5) + win) << 9;
        }
        __syncthreads();
    }

    auto load_chunk = [&](int c, int buf) {
        const uint32_t tbu = tbase + buf * STAGEB;
        const long kkB = (long)c << 6;
        const int tap = c >> 3, c0 = (c & 7) << 6;
#pragma unroll
        for (int it = 0; it < BM / 64; it++) {     // A: BM rows x 8 segs, 512 thr
            const int i = it * 512 + tid;
            const int row = i >> 3, seg = i & 7;
            long offA;
            if (gather) offA = (long)sBase[row * 27 + tap] + c0 + (seg << 3);
            else        offA = (long)(m0 + row) * ldA + kkB + (seg << 3);
            const uint32_t d = SWZ128((uint32_t)(row * 128 + seg * 16));
            cp16(tbu + d,          AHi + offA);
            cp16(tbu + ABYTES + d, ALo + offA);
        }
#pragma unroll
        for (int it = 0; it < 4; it++) {           // B: 256 rows x 8 segs
            const int i = it * 512 + tid;
            const int row = i >> 3, seg = i & 7;
            const long offB = (long)(n0 + row) * ldB + kkB + (seg << 3);
            const uint32_t d = SWZ128((uint32_t)(row * 128 + seg * 16));
            cp16(tbu + 2 * ABYTES + d,         BHi + offB);
            cp16(tbu + 2 * ABYTES + 32768 + d, BLo + offB);
        }
    };

    float acc[4][NT][4];
#pragma unroll
    for (int a = 0; a < 4; a++)
#pragma unroll
        for (int b = 0; b < NT; b++)
#pragma unroll
            for (int i = 0; i < 4; i++) acc[a][b][i] = 0.0f;

    const int a_r = lid & 15, a_ko = (lid >> 4) * 16;
    const int b_r = ((lid >> 4) << 3) + (lid & 7);
    const int b_ko = ((lid >> 3) & 1) * 16;

    const int nc = Ktot >> 6;
    load_chunk(0, 0);
    CP_COMMIT();

    for (int c = 0; c < nc; c++) {
        if (c + 1 < nc) { load_chunk(c + 1, (c + 1) & 1); CP_COMMIT(); CP_WAIT1(); }
        else            { CP_WAIT0(); }
        __syncthreads();

        const uint32_t tbu = tbase + (c & 1) * STAGEB;
#pragma unroll
        for (int ks = 0; ks < 4; ks++) {
            const int kb = ks * 32;
            uint32_t ah[4][4], al[4][4];
#pragma unroll
            for (int mt = 0; mt < 4; mt++) {
                const int row = wm * 64 + mt * 16 + a_r;
                const uint32_t off = SWZ128((uint32_t)(row * 128 + kb + a_ko));
                LDSM_X4(ah[mt], tbu + off);
                LDSM_X4(al[mt], tbu + ABYTES + off);
            }
#pragma unroll
            for (int p = 0; p < NP; p++) {
                const int row = wn * WNW + p * 16 + b_r;
                const uint32_t off = SWZ128((uint32_t)(row * 128 + kb + b_ko));
                uint32_t rh[4], rl[4];
                LDSM_X4(rh, tbu + 2 * ABYTES + off);
                LDSM_X4(rl, tbu + 2 * ABYTES + 32768 + off);
#pragma unroll
                for (int mt = 0; mt < 4; mt++) {
                    mma16816(acc[mt][2*p],   ah[mt], rh);
                    mma16816(acc[mt][2*p],   ah[mt], rl);
                    mma16816(acc[mt][2*p],   al[mt], rh);
                    mma16816(acc[mt][2*p+1], ah[mt], rh + 2);
                    mma16816(acc[mt][2*p+1], ah[mt], rl + 2);
                    mma16816(acc[mt][2*p+1], al[mt], rh + 2);
                }
            }
        }
        __syncthreads();
    }

    // epilogue
    const int er = lid >> 2, ec = (lid & 3) * 2;
#pragma unroll
    for (int mt = 0; mt < 4; mt++) {
#pragma unroll
        for (int nt = 0; nt < NT; nt++) {
            const int n = n0 + wn * WNW + nt * 8 + ec;
            float b0 = 0.f, b1 = 0.f;
            if (bias) { b0 = bias[n]; b1 = bias[n + 1]; }
#pragma unroll
            for (int half = 0; half < 2; half++) {
                const int m = m0 + wm * 64 + mt * 16 + er + half * 8;
                float v0 = acc[mt][nt][half * 2 + 0] * scale + b0;
                float v1 = acc[mt][nt][half * 2 + 1] * scale + b1;
                if (resid) {
                    const float2 rv = *(const float2*)(resid + (size_t)m * ldc + n);
                    v0 += rv.x; v1 += rv.y;
                }
                if (C)
                    *(float2*)(C + (size_t)m * ldc + n) = make_float2(v0, v1);
                if (outHi) {
                    bf16 h0 = __float2bfloat16(v0), h1 = __float2bfloat16(v1);
                    __nv_bfloat162 hh; hh.x = h0; hh.y = h1;
                    __nv_bfloat162 ll;
                    ll.x = __float2bfloat16(v0 - __bfloat162float(h0));
                    ll.y = __float2bfloat16(v1 - __bfloat162float(h1));
                    *(__nv_bfloat162*)(outHi + (size_t)m * ldc + n) = hh;
                    *(__nv_bfloat162*)(outLo + (size_t)m * ldc + n) = ll;
                }
            }
        }
    }
}

// ---------------- host orchestration ----------------
extern "C" void kernel_launch(void* const* d_in, const int* in_sizes, int n_in,
                              void* d_out, int out_size)
{
    const float* x    = (const float*)d_in[0];
    const float* r1g1 = (const float*)d_in[1];
    const float* r1w1 = (const float*)d_in[2];
    const float* r1b1 = (const float*)d_in[3];
    const float* r1g2 = (const float*)d_in[4];
    const float* r1w2 = (const float*)d_in[5];
    const float* r1b2 = (const float*)d_in[6];
    const float* atg  = (const float*)d_in[7];
    const float* qw   = (const float*)d_in[8];
    const float* qb   = (const float*)d_in[9];
    const float* kw   = (const float*)d_in[10];
    const float* kb   = (const float*)d_in[11];
    const float* vw   = (const float*)d_in[12];
    const float* vb   = (const float*)d_in[13];
    const float* pw   = (const float*)d_in[14];
    const float* pb   = (const float*)d_in[15];
    const float* r2g1 = (const float*)d_in[16];
    const float* r2w1 = (const float*)d_in[17];
    const float* r2b1 = (const float*)d_in[18];
    const float* r2g2 = (const float*)d_in[19];
    const float* r2w2 = (const float*)d_in[20];
    const float* r2b2 = (const float*)d_in[21];
    float* out = (float*)d_out;

    bf16 *nHi, *nLo, *wHi, *wLo, *qHi, *qLo, *kHi, *kLo, *vtHi, *vtLo, *pHi, *pLo;
    float *s, *t, *h, *y;
    cudaGetSymbolAddress((void**)&nHi, g_nHi);  cudaGetSymbolAddress((void**)&nLo, g_nLo);
    cudaGetSymbolAddress((void**)&wHi, g_wHi);  cudaGetSymbolAddress((void**)&wLo, g_wLo);
    cudaGetSymbolAddress((void**)&qHi, g_qHi);  cudaGetSymbolAddress((void**)&qLo, g_qLo);
    cudaGetSymbolAddress((void**)&kHi, g_kHi);  cudaGetSymbolAddress((void**)&kLo, g_kLo);
    cudaGetSymbolAddress((void**)&vtHi, g_vtHi); cudaGetSymbolAddress((void**)&vtLo, g_vtLo);
    cudaGetSymbolAddress((void**)&pHi, g_pHi);  cudaGetSymbolAddress((void**)&pLo, g_pLo);
    cudaGetSymbolAddress((void**)&s, g_s);
    cudaGetSymbolAddress((void**)&t, g_t);
    cudaGetSymbolAddress((void**)&h, g_h);
    cudaGetSymbolAddress((void**)&y, g_y);

    const int SMB128 = 1024 + 2 * (2 * 128 * 128 + 65536) + 128 * 27 * 4;  // 211456
    const int SMB64  = 1024 + 2 * (2 * 64 * 128 + 65536)  + 64 * 27 * 4;   // 171776
    cudaFuncSetAttribute(tc_gemm<128>, cudaFuncAttributeMaxDynamicSharedMemorySize, SMB128);
    cudaFuncSetAttribute(tc_gemm<64>,  cudaFuncAttributeMaxDynamicSharedMemorySize, SMB64);

    const dim3 gStd(2, 64);            // 128-row tiles
    const dim3 gNT(32, 64);            // scores
    const dim3 gAV(2, 128);            // 64-row tiles, descending-K
    const dim3 tBlk(32, 8);
    const dim3 gWT3(16, 432);
    const dim3 gWT1(16, 16);
    const dim3 gVT(16, 256);
    const float rs512 = 0.04419417382415922f;

    // ---- resnet 1 ----
    rmsnorm_split<<<SPOS, 128>>>(x, r1g1, nHi, nLo, 1);
    transpose_split<<<gWT3, tBlk>>>(r1w1, wHi, wLo, CONVK, CCH);
    tc_gemm<128><<<gStd, 512, SMB128>>>(nHi, nLo, CCH, wHi, wLo, CONVK, r1b1, nullptr, h, nullptr, nullptr, CCH, CONVK, TCG_GATHER, 1.0f);
    rmsnorm_split<<<SPOS, 128>>>(h, r1g2, nHi, nLo, 1);
    transpose_split<<<gWT3, tBlk>>>(r1w2, wHi, wLo, CONVK, CCH);
    tc_gemm<128><<<gStd, 512, SMB128>>>(nHi, nLo, CCH, wHi, wLo, CONVK, r1b2, x, y, nullptr, nullptr, CCH, CONVK, TCG_GATHER, 1.0f);

    // ---- attention ----
    rmsnorm_split<<<SPOS, 128>>>(y, atg, nHi, nLo, 0);
    transpose_split<<<gWT1, tBlk>>>(qw, wHi, wLo, CCH, CCH);
    tc_gemm<128><<<gStd, 512, SMB128>>>(nHi, nLo, CCH, wHi, wLo, CCH, qb, nullptr, nullptr, qHi, qLo, CCH, CCH, 0, 1.0f);
    transpose_split<<<gWT1, tBlk>>>(kw, wHi, wLo, CCH, CCH);
    tc_gemm<128><<<gStd, 512, SMB128>>>(nHi, nLo, CCH, wHi, wLo, CCH, kb, nullptr, nullptr, kHi, kLo, CCH, CCH, 0, 1.0f);
    transpose_split<<<gWT1, tBlk>>>(vw, wHi, wLo, CCH, CCH);
    tc_gemm<128><<<gStd, 512, SMB128>>>(nHi, nLo, CCH, wHi, wLo, CCH, vb, nullptr, t, nullptr, nullptr, CCH, CCH, 0, 1.0f);
    transpose_split<<<gVT, tBlk>>>(t, vtHi, vtLo, SPOS, CCH);

    tc_gemm<128><<<gNT, 512, SMB128>>>(qHi, qLo, CCH, kHi, kLo, CCH, nullptr, nullptr, s, nullptr, nullptr, SPOS, CCH, TCG_CAUSAL, rs512);
    softmax_split<<<SPOS, 256>>>(s, pHi, pLo);
    tc_gemm<64><<<gAV, 512, SMB64>>>(pHi, pLo, SPOS, vtHi, vtLo, SPOS, nullptr, nullptr, nullptr, qHi, qLo, CCH, SPOS, TCG_VARK, 1.0f);
    transpose_split<<<gWT1, tBlk>>>(pw, wHi, wLo, CCH, CCH);
    tc_gemm<128><<<gStd, 512, SMB128>>>(qHi, qLo, CCH, wHi, wLo, CCH, pb, y, h, nullptr, nullptr, CCH, CCH, 0, 1.0f);

    // ---- resnet 2 ----
    rmsnorm_split<<<SPOS, 128>>>(h, r2g1, nHi, nLo, 1);
    transpose_split<<<gWT3, tBlk>>>(r2w1, wHi, wLo, CONVK, CCH);
    tc_gemm<128><<<gStd, 512, SMB128>>>(nHi, nLo, CCH, wHi, wLo, CONVK, r2b1, nullptr, t, nullptr, nullptr, CCH, CONVK, TCG_GATHER, 1.0f);
    rmsnorm_split<<<SPOS, 128>>>(t, r2g2, nHi, nLo, 1);
    transpose_split<<<gWT3, tBlk>>>(r2w2, wHi, wLo, CONVK, CCH);
    tc_gemm<128><<<gStd, 512, SMB128>>>(nHi, nLo, CCH, wHi, wLo, CONVK, r2b2, h, out, nullptr, nullptr, CCH, CONVK, TCG_GATHER, 1.0f);
}